// round 11
// baseline (speedup 1.0000x reference)
#include <cuda_runtime.h>
#include <cuda_fp16.h>
#include <mma.h>
#include <math.h>
#include <stdint.h>

#define BB   4
#define NN   2048
#define DIMM 1024
#define HID  4096
#define NE   16
#define CAP  256
#define NTOK (BB*NN)          // 8192 tokens
#define NSLOT (NE*BB*CAP)     // 16384 expert slot rows
#define FLT_MIN_NORM 1.17549435e-38f
#define EXP_FTZ_CUT  (-87.336544f)

using namespace nvcuda;

// ------------------------- scratch (device globals) -------------------------
__device__ float  g_probs[NTOK*NE];
__device__ int    g_e1[NTOK], g_e2[NTOK];
__device__ float  g_g1[NTOK], g_g2[NTOK];
__device__ int    g_slot1[NTOK], g_slot2[NTOK];
__device__ int    g_slot_token[NSLOT];
__device__ int    g_cnt_total[BB*NE];
__device__ float  g_part_loss[BB*NE];
__device__ __half g_einh [(size_t)NSLOT*DIMM];       // 32 MB
__device__ __half g_hidh [(size_t)NSLOT*HID];        // 128 MB
__device__ __half g_eouth[(size_t)NSLOT*DIMM];       // 32 MB
__device__ __half g_w1h  [(size_t)NE*DIMM*HID];      // 128 MB
__device__ __half g_w2h  [(size_t)NE*HID*DIMM];      // 128 MB

// ------------------------- async-copy helpers --------------------------------
__device__ __forceinline__ uint32_t s2u(const void* p) {
    uint32_t a;
    asm("{ .reg .u64 t; cvta.to.shared.u64 t, %1; cvt.u32.u64 %0, t; }"
        : "=r"(a) : "l"(p));
    return a;
}
#define CP16(dst, src) \
    asm volatile("cp.async.cg.shared.global [%0], [%1], 16;" \
                 :: "r"(dst), "l"(src) : "memory")
#define CP_COMMIT() asm volatile("cp.async.commit_group;" ::: "memory")
#define CP_WAIT3()  asm volatile("cp.async.wait_group 3;" ::: "memory")
#define CP_WAIT0()  asm volatile("cp.async.wait_group 0;" ::: "memory")

// ------------------------------- init ---------------------------------------
__global__ void init_kernel() {
    int i = blockIdx.x * blockDim.x + threadIdx.x;
    if (i < NSLOT) g_slot_token[i] = -1;
}

// -------------------------- weight fp32 -> fp16 ------------------------------
__global__ void wconv_kernel(const float4* __restrict__ src, int which, int n4) {
    uint2* __restrict__ dst = which ? (uint2*)g_w2h : (uint2*)g_w1h;
    int i = blockIdx.x * blockDim.x + threadIdx.x;
    int stride = gridDim.x * blockDim.x;
    for (; i < n4; i += stride) {
        float4 v = src[i];
        __half2 h0 = __floats2half2_rn(v.x, v.y);
        __half2 h1 = __floats2half2_rn(v.z, v.w);
        uint2 o; o.x = *(uint32_t*)&h0; o.y = *(uint32_t*)&h1;
        dst[i] = o;
    }
}

// ------------------------------ gating ---------------------------------------
// Logits via warp-tree reduction (routing proven invariant to summation order
// in rounds 1/3/4); the FTZ softmax / argmax / gates_wo1 pipeline is GOLDEN
// and kept verbatim. One block (16 warps) per token.
__global__ void gating_kernel(const float* __restrict__ x,
                              const float* __restrict__ wg) {
    int tok  = blockIdx.x;
    int wid  = threadIdx.x >> 5;        // expert
    int lane = threadIdx.x & 31;
    const float* xr = x + (size_t)tok * DIMM;

    float acc = 0.f;
    #pragma unroll 8
    for (int d = lane; d < DIMM; d += 32)
        acc = fmaf(xr[d], wg[d * NE + wid], acc);
    #pragma unroll
    for (int o = 16; o; o >>= 1) acc += __shfl_xor_sync(0xffffffffu, acc, o);

    __shared__ float lg[NE];
    if (lane == 0) lg[wid] = acc;
    __syncthreads();

    if (threadIdx.x == 0) {
        float l[NE], p[NE];
        #pragma unroll
        for (int i = 0; i < NE; i++) l[i] = lg[i];

        float m = l[0];
        #pragma unroll
        for (int i = 1; i < NE; i++) m = fmaxf(m, l[i]);
        float s = 0.f;
        #pragma unroll
        for (int i = 0; i < NE; i++) {
            float t = l[i] - m;
            float pe = (t < EXP_FTZ_CUT) ? 0.f : expf(t);   // FTZ exp
            p[i] = pe; s = s + pe;
        }
        #pragma unroll
        for (int i = 0; i < NE; i++) {
            float q = p[i] / s;
            if (q < FLT_MIN_NORM) q = 0.f;                  // FTZ divide
            p[i] = q;
        }

        int i1 = 0; float p1 = p[0];
        #pragma unroll
        for (int i = 1; i < NE; i++) if (p[i] > p1) { p1 = p[i]; i1 = i; }
        float gw[NE];
        #pragma unroll
        for (int i = 0; i < NE; i++) gw[i] = (i == i1) ? 0.f : p[i];
        int i2 = 0; float p2v = gw[0];
        #pragma unroll
        for (int i = 1; i < NE; i++) if (gw[i] > p2v) { p2v = gw[i]; i2 = i; }

        float den = p1 + p2v + 1e-9f;
        g_e1[tok] = i1; g_e2[tok] = i2;
        g_g1[tok] = p1 / den; g_g2[tok] = p2v / den;
        #pragma unroll
        for (int i = 0; i < NE; i++) g_probs[tok * NE + i] = p[i];
    }
}

// --------------------------- capacity / assign -------------------------------
__global__ void assign_kernel() {
    const int T = 256, TPT = NN / T;
    int b = blockIdx.x / NE, e = blockIdx.x % NE;
    int t = threadIdx.x;
    __shared__ int s[T];

    int flag[TPT], loc[TPT]; int c = 0;
    #pragma unroll
    for (int i = 0; i < TPT; i++) {
        int n = t * TPT + i;
        int f = (g_e1[b * NN + n] == e);
        flag[i] = f; loc[i] = c; c += f;
    }
    s[t] = c; __syncthreads();
    for (int off = 1; off < T; off <<= 1) {
        int v = (t >= off) ? s[t - off] : 0;
        __syncthreads(); s[t] += v; __syncthreads();
    }
    int total = s[T - 1];
    int excl  = s[t] - c;
    #pragma unroll
    for (int i = 0; i < TPT; i++) {
        if (flag[i]) {
            int n = t * TPT + i, gi = b * NN + n;
            int pos = excl + loc[i];
            if (pos < CAP) {
                int slot = (e * BB + b) * CAP + pos;
                g_slot1[gi] = slot;
                g_slot_token[slot] = gi;
            } else g_slot1[gi] = -1;
        }
    }
    if (t == 0) g_cnt_total[b * NE + e] = total;
    int kept1 = total < CAP ? total : CAP;
    __syncthreads();

    c = 0;
    #pragma unroll
    for (int i = 0; i < TPT; i++) {
        int n = t * TPT + i;
        int f = (g_e2[b * NN + n] == e);
        flag[i] = f; loc[i] = c; c += f;
    }
    s[t] = c; __syncthreads();
    for (int off = 1; off < T; off <<= 1) {
        int v = (t >= off) ? s[t - off] : 0;
        __syncthreads(); s[t] += v; __syncthreads();
    }
    excl = s[t] - c;
    #pragma unroll
    for (int i = 0; i < TPT; i++) {
        if (flag[i]) {
            int n = t * TPT + i, gi = b * NN + n;
            int pos = excl + loc[i] + kept1;
            if (pos < CAP) {
                int slot = (e * BB + b) * CAP + pos;
                g_slot2[gi] = slot;
                g_slot_token[slot] = gi;
            } else g_slot2[gi] = -1;
        }
    }
}

// ------------------------------- gather (fp32 -> fp16) -----------------------
__global__ void gather_kernel(const float* __restrict__ x) {
    int row = blockIdx.x;
    int tok = g_slot_token[row];
    uint2* dst = (uint2*)(g_einh + (size_t)row * DIMM);
    int t = threadIdx.x;
    if (tok >= 0) {
        float4 v = ((const float4*)(x + (size_t)tok * DIMM))[t];
        __half2 h0 = __floats2half2_rn(v.x, v.y);
        __half2 h1 = __floats2half2_rn(v.z, v.w);
        uint2 o; o.x = *(uint32_t*)&h0; o.y = *(uint32_t*)&h1;
        dst[t] = o;
    } else {
        dst[t] = make_uint2(0u, 0u);
    }
}

// ------------ WMMA fp16 GEMM, 128x256 tile, 5-stage cp.async -----------------
// 8 warps as 2x4 grid of 64x64 warp tiles (4x4 m16n16k16 frags each).
__device__ __forceinline__ float gelu_exact(float v) {
    return 0.5f * v * (1.f + erff(v * 0.70710678118654752f));
}

template<int KDIM, int NDIM, bool FIRST>
__global__ void __launch_bounds__(256) hgemm(const float* __restrict__ bias) {
    const __half* __restrict__ A  = FIRST ? g_einh : g_hidh;
    const __half* __restrict__ Wh = FIRST ? g_w1h  : g_w2h;
    __half* __restrict__ C        = FIRST ? g_hidh : g_eouth;

    constexpr int BM = 128, BN = 256, BK = 32;
    constexpr int NC = KDIM / BK;
    constexpr int ALD = 40;                        // padded A row (halves)
    constexpr int BLD = 264;                       // padded B row (halves)
    constexpr int ABYTES = BM * ALD * 2;           // 10240
    constexpr int STAGE  = ABYTES + BK * BLD * 2;  // 27136
    constexpr int NSTG   = 5;                      // 135680 B smem

    extern __shared__ __align__(16) char dsm[];

    const int tid = threadIdx.x, wid = tid >> 5, lane = tid & 31;
    const int bx = blockIdx.x, by = blockIdx.y;
    const int rowBase = by * BM, colBase = bx * BN;
    const int e = rowBase >> 10;
    const __half* __restrict__ Wp = Wh + (size_t)e * KDIM * NDIM;
    const __half* __restrict__ Ap = A + (size_t)rowBase * KDIM;
    const uint32_t sbase = s2u(dsm);
    const int wm = (wid & 1) * 64, wn = (wid >> 1) * 64;

    wmma::fragment<wmma::accumulator, 16, 16, 16, float> acc[4][4];
    #pragma unroll
    for (int i = 0; i < 4; i++)
        #pragma unroll
        for (int j = 0; j < 4; j++) wmma::fill_fragment(acc[i][j], 0.f);

    auto issue = [&](int s, int c) {
        uint32_t ab = sbase + s * STAGE;
        #pragma unroll
        for (int i = 0; i < 2; i++) {
            int ch = tid + i * 256;               // 512 chunks: 128 rows x 64B
            int r = ch >> 2, q = ch & 3;
            CP16(ab + r * 80 + q * 16, Ap + (size_t)r * KDIM + c * BK + q * 8);
        }
        uint32_t bb = sbase + s * STAGE + ABYTES;
        #pragma unroll
        for (int i = 0; i < 4; i++) {
            int ch = tid + i * 256;               // 1024 chunks: 32 rows x 512B
            int r = ch >> 5, q = ch & 31;
            CP16(bb + r * 528 + q * 16,
                 Wp + (size_t)(c * BK + r) * NDIM + colBase + q * 8);
        }
    };

    #pragma unroll
    for (int s = 0; s < 4; s++) { issue(s, s); CP_COMMIT(); }

    int stg = 0;
    for (int c = 0; c < NC; c++) {
        CP_WAIT3();
        __syncthreads();
        if (c + 4 < NC) issue((stg + 4) % NSTG, c + 4);
        CP_COMMIT();                              // empty at tail keeps count

        const __half* As_ = (const __half*)(dsm + stg * STAGE);
        const __half* Bs_ = (const __half*)(dsm + stg * STAGE + ABYTES);
        #pragma unroll
        for (int kk = 0; kk < 2; kk++) {
            wmma::fragment<wmma::matrix_a, 16, 16, 16, half, wmma::row_major> af[4];
            wmma::fragment<wmma::matrix_b, 16, 16, 16, half, wmma::row_major> bf[4];
            #pragma unroll
            for (int i = 0; i < 4; i++)
                wmma::load_matrix_sync(af[i], As_ + (wm + i * 16) * ALD + kk * 16, ALD);
            #pragma unroll
            for (int j = 0; j < 4; j++)
                wmma::load_matrix_sync(bf[j], Bs_ + (kk * 16) * BLD + wn + j * 16, BLD);
            #pragma unroll
            for (int i = 0; i < 4; i++)
                #pragma unroll
                for (int j = 0; j < 4; j++)
                    wmma::mma_sync(acc[i][j], af[i], bf[j], acc[i][j]);
        }
        __syncthreads();
        stg = (stg + 1 == NSTG) ? 0 : stg + 1;
    }

    CP_WAIT0();
    __syncthreads();

    // ---- epilogue: per-warp 16x64 smem restage, fp16 vectorized stores ----
    float* epi = (float*)dsm + wid * 16 * 68;     // 16 rows x ldm 68
    #pragma unroll
    for (int i = 0; i < 4; i++) {
        #pragma unroll
        for (int j = 0; j < 4; j++)
            wmma::store_matrix_sync(epi + j * 16, acc[i][j], 68, wmma::mem_row_major);
        __syncwarp();
        int r0 = rowBase + wm + i * 16;
        int c0 = colBase + wn;
        #pragma unroll
        for (int q = 0; q < 4; q++) {
            int sid = q * 32 + lane;              // 128 chunks of 8 halves
            int row = sid >> 3, c8 = (sid & 7) * 8;
            float4 b0 = *(const float4*)(&bias[c0 + c8]);
            float4 b1 = *(const float4*)(&bias[c0 + c8 + 4]);
            const float* er = epi + row * 68 + c8;
            float v0 = er[0] + b0.x, v1 = er[1] + b0.y;
            float v2 = er[2] + b0.z, v3 = er[3] + b0.w;
            float v4 = er[4] + b1.x, v5 = er[5] + b1.y;
            float v6 = er[6] + b1.z, v7 = er[7] + b1.w;
            if (FIRST) {
                v0 = gelu_exact(v0); v1 = gelu_exact(v1);
                v2 = gelu_exact(v2); v3 = gelu_exact(v3);
                v4 = gelu_exact(v4); v5 = gelu_exact(v5);
                v6 = gelu_exact(v6); v7 = gelu_exact(v7);
            }
            __half2 h0 = __floats2half2_rn(v0, v1), h1 = __floats2half2_rn(v2, v3);
            __half2 h2 = __floats2half2_rn(v4, v5), h3 = __floats2half2_rn(v6, v7);
            uint4 o; o.x = *(uint32_t*)&h0; o.y = *(uint32_t*)&h1;
            o.z = *(uint32_t*)&h2; o.w = *(uint32_t*)&h3;
            *(uint4*)(&C[(size_t)(r0 + row) * NDIM + c0 + c8]) = o;
        }
        __syncwarp();
    }
}

// ------------------------------- combine (fp16 eout) -------------------------
__global__ void combine_kernel(float* __restrict__ out) {
    int tok = blockIdx.x;
    int t   = threadIdx.x;                         // 256 threads x 4 floats
    int s1 = g_slot1[tok], s2 = g_slot2[tok];
    float g1 = (s1 >= 0) ? g_g1[tok] : 0.f;
    float g2 = (s2 >= 0) ? g_g2[tok] : 0.f;
    float4 v = make_float4(0.f, 0.f, 0.f, 0.f);
    if (s1 >= 0) {
        uint2 raw = ((const uint2*)(g_eouth + (size_t)s1 * DIMM))[t];
        float2 a0 = __half22float2(*(__half2*)&raw.x);
        float2 a1 = __half22float2(*(__half2*)&raw.y);
        v.x += g1 * a0.x; v.y += g1 * a0.y; v.z += g1 * a1.x; v.w += g1 * a1.y;
    }
    if (s2 >= 0) {
        uint2 raw = ((const uint2*)(g_eouth + (size_t)s2 * DIMM))[t];
        float2 a0 = __half22float2(*(__half2*)&raw.x);
        float2 a1 = __half22float2(*(__half2*)&raw.y);
        v.x += g2 * a0.x; v.y += g2 * a0.y; v.z += g2 * a1.x; v.w += g2 * a1.y;
    }
    ((float4*)(out + (size_t)tok * DIMM))[t] = v;
}

// -------------------------------- loss ---------------------------------------
__global__ void loss_part_kernel() {
    int be = blockIdx.x;
    int b = be / NE, e = be % NE;
    __shared__ float s[256];
    float acc = 0.f;
    for (int n = threadIdx.x; n < NN; n += 256)
        acc += g_probs[(size_t)(b * NN + n) * NE + e];
    s[threadIdx.x] = acc; __syncthreads();
    for (int off = 128; off; off >>= 1) {
        if (threadIdx.x < off) s[threadIdx.x] += s[threadIdx.x + off];
        __syncthreads();
    }
    if (threadIdx.x == 0)
        g_part_loss[be] = (s[0] / (float)NN) *
                          ((float)g_cnt_total[be] / (float)NN);
}

__global__ void loss_final_kernel(float* __restrict__ out) {
    __shared__ float s[64];
    int t = threadIdx.x;
    s[t] = g_part_loss[t]; __syncthreads();
    for (int off = 32; off; off >>= 1) {
        if (t < off) s[t] += s[t + off];
        __syncthreads();
    }
    if (t == 0) out[(size_t)NTOK * DIMM] = s[0] * 0.04f;
}

// ------------------------------- launch --------------------------------------
extern "C" void kernel_launch(void* const* d_in, const int* in_sizes, int n_in,
                              void* d_out, int out_size) {
    const float* x  = (const float*)d_in[0];
    const float* wg = (const float*)d_in[1];
    const float* w1 = (const float*)d_in[2];
    const float* w2 = (const float*)d_in[3];
    const float* b1 = (const float*)d_in[4];
    const float* b2 = (const float*)d_in[5];
    float* out = (float*)d_out;

    constexpr int SMEM = 5 * 27136;   // 135680
    cudaFuncSetAttribute(hgemm<DIMM, HID,  true >,
                         cudaFuncAttributeMaxDynamicSharedMemorySize, SMEM);
    cudaFuncSetAttribute(hgemm<HID,  DIMM, false>,
                         cudaFuncAttributeMaxDynamicSharedMemorySize, SMEM);

    const int W4 = NE * DIMM * HID / 4;
    // order chosen so ncu (-s 5 -c 1) profiles hgemm1 (launch index 5)
    init_kernel<<<(NSLOT + 255) / 256, 256>>>();                       // 0
    gating_kernel<<<NTOK, 512>>>(x, wg);                               // 1
    assign_kernel<<<BB * NE, 256>>>();                                 // 2
    gather_kernel<<<NSLOT, 256>>>(x);                                  // 3
    wconv_kernel<<<8192, 256>>>((const float4*)w1, 0, W4);             // 4
    hgemm<DIMM, HID,  true ><<<dim3(HID / 256, NSLOT / 128), 256, SMEM>>>(b1); // 5
    wconv_kernel<<<8192, 256>>>((const float4*)w2, 1, W4);             // 6
    hgemm<HID,  DIMM, false><<<dim3(DIMM / 256, NSLOT / 128), 256, SMEM>>>(b2); // 7
    combine_kernel<<<NTOK, 256>>>(out);                                // 8
    loss_part_kernel<<<BB * NE, 256>>>();                              // 9
    if (out_size > NTOK * DIMM)
        loss_final_kernel<<<1, 64>>>(out);                             // 10
}

// round 12
// speedup vs baseline: 1.0934x; 1.0934x over previous
#include <cuda_runtime.h>
#include <cuda_fp16.h>
#include <mma.h>
#include <math.h>
#include <stdint.h>

#define BB   4
#define NN   2048
#define DIMM 1024
#define HID  4096
#define NE   16
#define CAP  256
#define NTOK (BB*NN)          // 8192 tokens
#define NSLOT (NE*BB*CAP)     // 16384 expert slot rows
#define FLT_MIN_NORM 1.17549435e-38f
#define EXP_FTZ_CUT  (-87.336544f)

using namespace nvcuda;

// ------------------------- scratch (device globals) -------------------------
__device__ float  g_probs[NTOK*NE];
__device__ int    g_e1[NTOK], g_e2[NTOK];
__device__ float  g_g1[NTOK], g_g2[NTOK];
__device__ int    g_slot1[NTOK], g_slot2[NTOK];
__device__ int    g_slot_token[NSLOT];
__device__ int    g_cnt_total[BB*NE];
__device__ float  g_part_loss[BB*NE];
__device__ __half g_einh [(size_t)NSLOT*DIMM];       // 32 MB
__device__ __half g_hidh [(size_t)NSLOT*HID];        // 128 MB
__device__ __half g_eouth[(size_t)NSLOT*DIMM];       // 32 MB
__device__ __half g_w1h  [(size_t)NE*DIMM*HID];      // 128 MB
__device__ __half g_w2h  [(size_t)NE*HID*DIMM];      // 128 MB

// ------------------------- async-copy helpers --------------------------------
__device__ __forceinline__ uint32_t s2u(const void* p) {
    uint32_t a;
    asm("{ .reg .u64 t; cvta.to.shared.u64 t, %1; cvt.u32.u64 %0, t; }"
        : "=r"(a) : "l"(p));
    return a;
}
#define CP16(dst, src) \
    asm volatile("cp.async.cg.shared.global [%0], [%1], 16;" \
                 :: "r"(dst), "l"(src) : "memory")
#define CP_COMMIT() asm volatile("cp.async.commit_group;" ::: "memory")
#define CP_WAIT2()  asm volatile("cp.async.wait_group 2;" ::: "memory")

// ------------------------------- init ---------------------------------------
__global__ void init_kernel() {
    int i = blockIdx.x * blockDim.x + threadIdx.x;
    if (i < NSLOT) g_slot_token[i] = -1;
}

// -------------------------- weight fp32 -> fp16 ------------------------------
__global__ void wconv_kernel(const float4* __restrict__ src, int which, int n4) {
    uint2* __restrict__ dst = which ? (uint2*)g_w2h : (uint2*)g_w1h;
    int i = blockIdx.x * blockDim.x + threadIdx.x;
    int stride = gridDim.x * blockDim.x;
    for (; i < n4; i += stride) {
        float4 v = src[i];
        __half2 h0 = __floats2half2_rn(v.x, v.y);
        __half2 h1 = __floats2half2_rn(v.z, v.w);
        uint2 o; o.x = *(uint32_t*)&h0; o.y = *(uint32_t*)&h1;
        dst[i] = o;
    }
}

// ------------------------------ gating ---------------------------------------
// Logits via warp-tree reduction (routing invariant to summation order, proven
// rounds 1/3/4). FTZ softmax / argmax / gates_wo1 pipeline is GOLDEN.
__global__ void gating_kernel(const float* __restrict__ x,
                              const float* __restrict__ wg) {
    int tok  = blockIdx.x;
    int wid  = threadIdx.x >> 5;        // expert
    int lane = threadIdx.x & 31;
    const float* xr = x + (size_t)tok * DIMM;

    float acc = 0.f;
    #pragma unroll 8
    for (int d = lane; d < DIMM; d += 32)
        acc = fmaf(xr[d], wg[d * NE + wid], acc);
    #pragma unroll
    for (int o = 16; o; o >>= 1) acc += __shfl_xor_sync(0xffffffffu, acc, o);

    __shared__ float lg[NE];
    if (lane == 0) lg[wid] = acc;
    __syncthreads();

    if (threadIdx.x == 0) {
        float l[NE], p[NE];
        #pragma unroll
        for (int i = 0; i < NE; i++) l[i] = lg[i];

        float m = l[0];
        #pragma unroll
        for (int i = 1; i < NE; i++) m = fmaxf(m, l[i]);
        float s = 0.f;
        #pragma unroll
        for (int i = 0; i < NE; i++) {
            float t = l[i] - m;
            float pe = (t < EXP_FTZ_CUT) ? 0.f : expf(t);   // FTZ exp
            p[i] = pe; s = s + pe;
        }
        #pragma unroll
        for (int i = 0; i < NE; i++) {
            float q = p[i] / s;
            if (q < FLT_MIN_NORM) q = 0.f;                  // FTZ divide
            p[i] = q;
        }

        int i1 = 0; float p1 = p[0];
        #pragma unroll
        for (int i = 1; i < NE; i++) if (p[i] > p1) { p1 = p[i]; i1 = i; }
        float gw[NE];
        #pragma unroll
        for (int i = 0; i < NE; i++) gw[i] = (i == i1) ? 0.f : p[i];
        int i2 = 0; float p2v = gw[0];
        #pragma unroll
        for (int i = 1; i < NE; i++) if (gw[i] > p2v) { p2v = gw[i]; i2 = i; }

        float den = p1 + p2v + 1e-9f;
        g_e1[tok] = i1; g_e2[tok] = i2;
        g_g1[tok] = p1 / den; g_g2[tok] = p2v / den;
        #pragma unroll
        for (int i = 0; i < NE; i++) g_probs[tok * NE + i] = p[i];
    }
}

// --------------------------- capacity / assign -------------------------------
__global__ void assign_kernel() {
    const int T = 256, TPT = NN / T;
    int b = blockIdx.x / NE, e = blockIdx.x % NE;
    int t = threadIdx.x;
    __shared__ int s[T];

    int flag[TPT], loc[TPT]; int c = 0;
    #pragma unroll
    for (int i = 0; i < TPT; i++) {
        int n = t * TPT + i;
        int f = (g_e1[b * NN + n] == e);
        flag[i] = f; loc[i] = c; c += f;
    }
    s[t] = c; __syncthreads();
    for (int off = 1; off < T; off <<= 1) {
        int v = (t >= off) ? s[t - off] : 0;
        __syncthreads(); s[t] += v; __syncthreads();
    }
    int total = s[T - 1];
    int excl  = s[t] - c;
    #pragma unroll
    for (int i = 0; i < TPT; i++) {
        if (flag[i]) {
            int n = t * TPT + i, gi = b * NN + n;
            int pos = excl + loc[i];
            if (pos < CAP) {
                int slot = (e * BB + b) * CAP + pos;
                g_slot1[gi] = slot;
                g_slot_token[slot] = gi;
            } else g_slot1[gi] = -1;
        }
    }
    if (t == 0) g_cnt_total[b * NE + e] = total;
    int kept1 = total < CAP ? total : CAP;
    __syncthreads();

    c = 0;
    #pragma unroll
    for (int i = 0; i < TPT; i++) {
        int n = t * TPT + i;
        int f = (g_e2[b * NN + n] == e);
        flag[i] = f; loc[i] = c; c += f;
    }
    s[t] = c; __syncthreads();
    for (int off = 1; off < T; off <<= 1) {
        int v = (t >= off) ? s[t - off] : 0;
        __syncthreads(); s[t] += v; __syncthreads();
    }
    excl = s[t] - c;
    #pragma unroll
    for (int i = 0; i < TPT; i++) {
        if (flag[i]) {
            int n = t * TPT + i, gi = b * NN + n;
            int pos = excl + loc[i] + kept1;
            if (pos < CAP) {
                int slot = (e * BB + b) * CAP + pos;
                g_slot2[gi] = slot;
                g_slot_token[slot] = gi;
            } else g_slot2[gi] = -1;
        }
    }
}

// ------------------------------- gather (fp32 -> fp16) -----------------------
__global__ void gather_kernel(const float* __restrict__ x) {
    int row = blockIdx.x;
    int tok = g_slot_token[row];
    uint2* dst = (uint2*)(g_einh + (size_t)row * DIMM);
    int t = threadIdx.x;
    if (tok >= 0) {
        float4 v = ((const float4*)(x + (size_t)tok * DIMM))[t];
        __half2 h0 = __floats2half2_rn(v.x, v.y);
        __half2 h1 = __floats2half2_rn(v.z, v.w);
        uint2 o; o.x = *(uint32_t*)&h0; o.y = *(uint32_t*)&h1;
        dst[t] = o;
    } else {
        dst[t] = make_uint2(0u, 0u);
    }
}

// ----------------- WMMA fp16 GEMM, cp.async 4-stage pipeline -----------------
// (round-10 proven config: 128x128x32, 8 warps x 32x64, 2 CTAs/SM)
__device__ __forceinline__ float gelu_exact(float v) {
    return 0.5f * v * (1.f + erff(v * 0.70710678118654752f));
}

template<int KDIM, int NDIM, bool FIRST>
__global__ void __launch_bounds__(256, 2) hgemm(const float* __restrict__ bias) {
    const __half* __restrict__ A  = FIRST ? g_einh : g_hidh;
    const __half* __restrict__ Wh = FIRST ? g_w1h  : g_w2h;
    __half* __restrict__ C        = FIRST ? g_hidh : g_eouth;

    constexpr int BM = 128, BN = 128, BK = 32;
    constexpr int NC = KDIM / BK;
    constexpr int ALD = 40;                       // halves per padded A row
    constexpr int BLD = 136;                      // halves per padded B row
    constexpr int ABYTES = BM * ALD * 2;          // 10240
    constexpr int STAGE  = ABYTES + BK * BLD * 2; // 18944

    extern __shared__ __align__(16) char dsm[];   // 4*STAGE = 75776 B

    const int tid = threadIdx.x, wid = tid >> 5, lane = tid & 31;
    const int bx = blockIdx.x, by = blockIdx.y;
    const int rowBase = by * BM, colBase = bx * BN;
    const int e = rowBase >> 10;
    const __half* __restrict__ Wp = Wh + (size_t)e * KDIM * NDIM;
    const __half* __restrict__ Ap = A + (size_t)rowBase * KDIM;
    const uint32_t sbase = s2u(dsm);
    const int wm = (wid & 3) * 32, wn = (wid >> 2) * 64;

    wmma::fragment<wmma::accumulator, 16, 16, 16, float> acc[2][4];
    #pragma unroll
    for (int i = 0; i < 2; i++)
        #pragma unroll
        for (int j = 0; j < 4; j++) wmma::fill_fragment(acc[i][j], 0.f);

    auto issue = [&](int s, int c) {
        uint32_t ab = sbase + s * STAGE;
        #pragma unroll
        for (int i = 0; i < 2; i++) {
            int ch = tid + i * 256;               // 512 chunks: 128 rows x 64B
            int r = ch >> 2, q = ch & 3;
            CP16(ab + r * 80 + q * 16, Ap + (size_t)r * KDIM + c * BK + q * 8);
        }
        uint32_t bb = sbase + s * STAGE + ABYTES;
        #pragma unroll
        for (int i = 0; i < 2; i++) {
            int ch = tid + i * 256;               // 512 chunks: 32 rows x 256B
            int r = ch >> 4, q = ch & 15;
            CP16(bb + r * 272 + q * 16,
                 Wp + (size_t)(c * BK + r) * NDIM + colBase + q * 8);
        }
    };

    #pragma unroll
    for (int s = 0; s < 3; s++) { issue(s, s); CP_COMMIT(); }

    for (int c = 0; c < NC; c++) {
        CP_WAIT2();
        __syncthreads();
        if (c + 3 < NC) issue((c + 3) & 3, c + 3);
        CP_COMMIT();                              // empty group at tail keeps count

        const __half* As_ = (const __half*)(dsm + (c & 3) * STAGE);
        const __half* Bs_ = (const __half*)(dsm + (c & 3) * STAGE + ABYTES);
        #pragma unroll
        for (int kk = 0; kk < 2; kk++) {
            wmma::fragment<wmma::matrix_a, 16, 16, 16, half, wmma::row_major> af[2];
            wmma::fragment<wmma::matrix_b, 16, 16, 16, half, wmma::row_major> bf[4];
            wmma::load_matrix_sync(af[0], As_ + (wm     ) * ALD + kk * 16, ALD);
            wmma::load_matrix_sync(af[1], As_ + (wm + 16) * ALD + kk * 16, ALD);
            #pragma unroll
            for (int j = 0; j < 4; j++)
                wmma::load_matrix_sync(bf[j], Bs_ + (kk * 16) * BLD + wn + j * 16, BLD);
            #pragma unroll
            for (int i = 0; i < 2; i++)
                #pragma unroll
                for (int j = 0; j < 4; j++)
                    wmma::mma_sync(acc[i][j], af[i], bf[j], acc[i][j]);
        }
        __syncthreads();
    }

    // ---- epilogue: restage 16x64 per warp in smem, fp16 vectorized stores ----
    float* epi = (float*)dsm + wid * 16 * 68;     // 16 rows x ldm 68
    #pragma unroll
    for (int i = 0; i < 2; i++) {
        #pragma unroll
        for (int j = 0; j < 4; j++)
            wmma::store_matrix_sync(epi + j * 16, acc[i][j], 68, wmma::mem_row_major);
        __syncwarp();
        int r0 = rowBase + wm + i * 16;
        int c0 = colBase + wn;
        #pragma unroll
        for (int q = 0; q < 4; q++) {
            int sid = q * 32 + lane;
            int row = sid >> 3, c8 = (sid & 7) * 8;
            float4 b0 = *(const float4*)(&bias[c0 + c8]);
            float4 b1 = *(const float4*)(&bias[c0 + c8 + 4]);
            const float* er = epi + row * 68 + c8;
            float v0 = er[0] + b0.x, v1 = er[1] + b0.y;
            float v2 = er[2] + b0.z, v3 = er[3] + b0.w;
            float v4 = er[4] + b1.x, v5 = er[5] + b1.y;
            float v6 = er[6] + b1.z, v7 = er[7] + b1.w;
            if (FIRST) {
                v0 = gelu_exact(v0); v1 = gelu_exact(v1);
                v2 = gelu_exact(v2); v3 = gelu_exact(v3);
                v4 = gelu_exact(v4); v5 = gelu_exact(v5);
                v6 = gelu_exact(v6); v7 = gelu_exact(v7);
            }
            __half2 h0 = __floats2half2_rn(v0, v1), h1 = __floats2half2_rn(v2, v3);
            __half2 h2 = __floats2half2_rn(v4, v5), h3 = __floats2half2_rn(v6, v7);
            uint4 o; o.x = *(uint32_t*)&h0; o.y = *(uint32_t*)&h1;
            o.z = *(uint32_t*)&h2; o.w = *(uint32_t*)&h3;
            *(uint4*)(&C[(size_t)(r0 + row) * NDIM + c0 + c8]) = o;
        }
        __syncwarp();
    }
}

// ------------------------------- combine (fp16 eout) -------------------------
__global__ void combine_kernel(float* __restrict__ out) {
    int tok = blockIdx.x;
    int t   = threadIdx.x;                         // 256 threads x 4 floats
    int s1 = g_slot1[tok], s2 = g_slot2[tok];
    float g1 = (s1 >= 0) ? g_g1[tok] : 0.f;
    float g2 = (s2 >= 0) ? g_g2[tok] : 0.f;
    float4 v = make_float4(0.f, 0.f, 0.f, 0.f);
    if (s1 >= 0) {
        uint2 raw = ((const uint2*)(g_eouth + (size_t)s1 * DIMM))[t];
        float2 a0 = __half22float2(*(__half2*)&raw.x);
        float2 a1 = __half22float2(*(__half2*)&raw.y);
        v.x += g1 * a0.x; v.y += g1 * a0.y; v.z += g1 * a1.x; v.w += g1 * a1.y;
    }
    if (s2 >= 0) {
        uint2 raw = ((const uint2*)(g_eouth + (size_t)s2 * DIMM))[t];
        float2 a0 = __half22float2(*(__half2*)&raw.x);
        float2 a1 = __half22float2(*(__half2*)&raw.y);
        v.x += g2 * a0.x; v.y += g2 * a0.y; v.z += g2 * a1.x; v.w += g2 * a1.y;
    }
    ((float4*)(out + (size_t)tok * DIMM))[t] = v;
}

// -------------------------------- loss ---------------------------------------
__global__ void loss_part_kernel() {
    int be = blockIdx.x;
    int b = be / NE, e = be % NE;
    __shared__ float s[256];
    float acc = 0.f;
    for (int n = threadIdx.x; n < NN; n += 256)
        acc += g_probs[(size_t)(b * NN + n) * NE + e];
    s[threadIdx.x] = acc; __syncthreads();
    for (int off = 128; off; off >>= 1) {
        if (threadIdx.x < off) s[threadIdx.x] += s[threadIdx.x + off];
        __syncthreads();
    }
    if (threadIdx.x == 0)
        g_part_loss[be] = (s[0] / (float)NN) *
                          ((float)g_cnt_total[be] / (float)NN);
}

__global__ void loss_final_kernel(float* __restrict__ out) {
    __shared__ float s[64];
    int t = threadIdx.x;
    s[t] = g_part_loss[t]; __syncthreads();
    for (int off = 32; off; off >>= 1) {
        if (t < off) s[t] += s[t + off];
        __syncthreads();
    }
    if (t == 0) out[(size_t)NTOK * DIMM] = s[0] * 0.04f;
}

// ------------------------------- launch --------------------------------------
extern "C" void kernel_launch(void* const* d_in, const int* in_sizes, int n_in,
                              void* d_out, int out_size) {
    const float* x  = (const float*)d_in[0];
    const float* wg = (const float*)d_in[1];
    const float* w1 = (const float*)d_in[2];
    const float* w2 = (const float*)d_in[3];
    const float* b1 = (const float*)d_in[4];
    const float* b2 = (const float*)d_in[5];
    float* out = (float*)d_out;

    constexpr int SMEM = 4 * 18944;   // 75776
    cudaFuncSetAttribute(hgemm<DIMM, HID,  true >,
                         cudaFuncAttributeMaxDynamicSharedMemorySize, SMEM);
    cudaFuncSetAttribute(hgemm<HID,  DIMM, false>,
                         cudaFuncAttributeMaxDynamicSharedMemorySize, SMEM);

    const int W4 = NE * DIMM * HID / 4;
    init_kernel<<<(NSLOT + 255) / 256, 256>>>();                       // 0
    gating_kernel<<<NTOK, 512>>>(x, wg);                               // 1
    assign_kernel<<<BB * NE, 256>>>();                                 // 2
    gather_kernel<<<NSLOT, 256>>>(x);                                  // 3
    wconv_kernel<<<8192, 256>>>((const float4*)w1, 0, W4);             // 4
    hgemm<DIMM, HID,  true ><<<dim3(HID / 128, NSLOT / 128), 256, SMEM>>>(b1); // 5
    wconv_kernel<<<8192, 256>>>((const float4*)w2, 1, W4);             // 6
    hgemm<HID,  DIMM, false><<<dim3(DIMM / 128, NSLOT / 128), 256, SMEM>>>(b2); // 7
    combine_kernel<<<NTOK, 256>>>(out);                                // 8
    loss_part_kernel<<<BB * NE, 256>>>();                              // 9
    if (out_size > NTOK * DIMM)
        loss_final_kernel<<<1, 64>>>(out);                             // 10
}

// round 13
// speedup vs baseline: 1.0988x; 1.0049x over previous
#include <cuda_runtime.h>
#include <cuda_fp16.h>
#include <mma.h>
#include <math.h>
#include <stdint.h>

#define BB   4
#define NN   2048
#define DIMM 1024
#define HID  4096
#define NE   16
#define CAP  256
#define NTOK (BB*NN)          // 8192 tokens
#define NSLOT (NE*BB*CAP)     // 16384 expert slot rows
#define FLT_MIN_NORM 1.17549435e-38f
#define EXP_FTZ_CUT  (-87.336544f)

using namespace nvcuda;

// ------------------------- scratch (device globals) -------------------------
__device__ float  g_probs[NTOK*NE];
__device__ int    g_e1[NTOK], g_e2[NTOK];
__device__ float  g_g1[NTOK], g_g2[NTOK];
__device__ int    g_slot1[NTOK], g_slot2[NTOK];
__device__ int    g_slot_token[NSLOT];
__device__ int    g_cnt_total[BB*NE];
__device__ float  g_part_loss[BB*NE];
__device__ __half g_einh [(size_t)NSLOT*DIMM];       // 32 MB
__device__ __half g_hidh [(size_t)NSLOT*HID];        // 128 MB
__device__ __half g_eouth[(size_t)NSLOT*DIMM];       // 32 MB
__device__ __half g_w1h  [(size_t)NE*DIMM*HID];      // 128 MB
__device__ __half g_w2h  [(size_t)NE*HID*DIMM];      // 128 MB

// ------------------------- async-copy helpers --------------------------------
__device__ __forceinline__ uint32_t s2u(const void* p) {
    uint32_t a;
    asm("{ .reg .u64 t; cvta.to.shared.u64 t, %1; cvt.u32.u64 %0, t; }"
        : "=r"(a) : "l"(p));
    return a;
}
#define CP16(dst, src) \
    asm volatile("cp.async.cg.shared.global [%0], [%1], 16;" \
                 :: "r"(dst), "l"(src) : "memory")
#define CP_COMMIT() asm volatile("cp.async.commit_group;" ::: "memory")
#define CP_WAIT2()  asm volatile("cp.async.wait_group 2;" ::: "memory")

// ------------------------------ gating ---------------------------------------
// Logits via warp-tree reduction (routing invariant to summation order, proven
// rounds 1/3/4). FTZ softmax / argmax / gates_wo1 pipeline is GOLDEN.
__global__ void gating_kernel(const float* __restrict__ x,
                              const float* __restrict__ wg) {
    int tok  = blockIdx.x;
    int wid  = threadIdx.x >> 5;        // expert
    int lane = threadIdx.x & 31;
    const float* xr = x + (size_t)tok * DIMM;

    float acc = 0.f;
    #pragma unroll 8
    for (int d = lane; d < DIMM; d += 32)
        acc = fmaf(xr[d], wg[d * NE + wid], acc);
    #pragma unroll
    for (int o = 16; o; o >>= 1) acc += __shfl_xor_sync(0xffffffffu, acc, o);

    __shared__ float lg[NE];
    if (lane == 0) lg[wid] = acc;
    __syncthreads();

    if (threadIdx.x == 0) {
        float l[NE], p[NE];
        #pragma unroll
        for (int i = 0; i < NE; i++) l[i] = lg[i];

        float m = l[0];
        #pragma unroll
        for (int i = 1; i < NE; i++) m = fmaxf(m, l[i]);
        float s = 0.f;
        #pragma unroll
        for (int i = 0; i < NE; i++) {
            float t = l[i] - m;
            float pe = (t < EXP_FTZ_CUT) ? 0.f : expf(t);   // FTZ exp
            p[i] = pe; s = s + pe;
        }
        #pragma unroll
        for (int i = 0; i < NE; i++) {
            float q = p[i] / s;
            if (q < FLT_MIN_NORM) q = 0.f;                  // FTZ divide
            p[i] = q;
        }

        int i1 = 0; float p1 = p[0];
        #pragma unroll
        for (int i = 1; i < NE; i++) if (p[i] > p1) { p1 = p[i]; i1 = i; }
        float gw[NE];
        #pragma unroll
        for (int i = 0; i < NE; i++) gw[i] = (i == i1) ? 0.f : p[i];
        int i2 = 0; float p2v = gw[0];
        #pragma unroll
        for (int i = 1; i < NE; i++) if (gw[i] > p2v) { p2v = gw[i]; i2 = i; }

        float den = p1 + p2v + 1e-9f;
        g_e1[tok] = i1; g_e2[tok] = i2;
        g_g1[tok] = p1 / den; g_g2[tok] = p2v / den;
        #pragma unroll
        for (int i = 0; i < NE; i++) g_probs[tok * NE + i] = p[i];
    }
}

// ---------------- capacity / assign (slot-segment clear fused in) ------------
__global__ void assign_kernel() {
    const int T = 256, TPT = NN / T;
    int b = blockIdx.x / NE, e = blockIdx.x % NE;
    int t = threadIdx.x;
    __shared__ int s[T];

    // clear this block's own slot segment (replaces init_kernel)
    g_slot_token[(e * BB + b) * CAP + t] = -1;
    __syncthreads();

    int flag[TPT], loc[TPT]; int c = 0;
    #pragma unroll
    for (int i = 0; i < TPT; i++) {
        int n = t * TPT + i;
        int f = (g_e1[b * NN + n] == e);
        flag[i] = f; loc[i] = c; c += f;
    }
    s[t] = c; __syncthreads();
    for (int off = 1; off < T; off <<= 1) {
        int v = (t >= off) ? s[t - off] : 0;
        __syncthreads(); s[t] += v; __syncthreads();
    }
    int total = s[T - 1];
    int excl  = s[t] - c;
    #pragma unroll
    for (int i = 0; i < TPT; i++) {
        if (flag[i]) {
            int n = t * TPT + i, gi = b * NN + n;
            int pos = excl + loc[i];
            if (pos < CAP) {
                int slot = (e * BB + b) * CAP + pos;
                g_slot1[gi] = slot;
                g_slot_token[slot] = gi;
            } else g_slot1[gi] = -1;
        }
    }
    if (t == 0) g_cnt_total[b * NE + e] = total;
    int kept1 = total < CAP ? total : CAP;
    __syncthreads();

    c = 0;
    #pragma unroll
    for (int i = 0; i < TPT; i++) {
        int n = t * TPT + i;
        int f = (g_e2[b * NN + n] == e);
        flag[i] = f; loc[i] = c; c += f;
    }
    s[t] = c; __syncthreads();
    for (int off = 1; off < T; off <<= 1) {
        int v = (t >= off) ? s[t - off] : 0;
        __syncthreads(); s[t] += v; __syncthreads();
    }
    excl = s[t] - c;
    #pragma unroll
    for (int i = 0; i < TPT; i++) {
        if (flag[i]) {
            int n = t * TPT + i, gi = b * NN + n;
            int pos = excl + loc[i] + kept1;
            if (pos < CAP) {
                int slot = (e * BB + b) * CAP + pos;
                g_slot2[gi] = slot;
                g_slot_token[slot] = gi;
            } else g_slot2[gi] = -1;
        }
    }
}

// ------------- gather (fp32 -> fp16) + w1 conversion, fused ------------------
// blocks [0, NSLOT)            : gather token rows into g_einh
// blocks [NSLOT, NSLOT+8192)   : convert w1 fp32 -> g_w1h (grid-stride)
__global__ void gather_wconv1_kernel(const float* __restrict__ x,
                                     const float4* __restrict__ w1src, int n4) {
    if (blockIdx.x < NSLOT) {
        int row = blockIdx.x;
        int tok = g_slot_token[row];
        uint2* dst = (uint2*)(g_einh + (size_t)row * DIMM);
        int t = threadIdx.x;
        if (tok >= 0) {
            float4 v = ((const float4*)(x + (size_t)tok * DIMM))[t];
            __half2 h0 = __floats2half2_rn(v.x, v.y);
            __half2 h1 = __floats2half2_rn(v.z, v.w);
            uint2 o; o.x = *(uint32_t*)&h0; o.y = *(uint32_t*)&h1;
            dst[t] = o;
        } else {
            dst[t] = make_uint2(0u, 0u);
        }
    } else {
        uint2* __restrict__ dst = (uint2*)g_w1h;
        int i = (blockIdx.x - NSLOT) * blockDim.x + threadIdx.x;
        int stride = 8192 * blockDim.x;
        for (; i < n4; i += stride) {
            float4 v = w1src[i];
            __half2 h0 = __floats2half2_rn(v.x, v.y);
            __half2 h1 = __floats2half2_rn(v.z, v.w);
            uint2 o; o.x = *(uint32_t*)&h0; o.y = *(uint32_t*)&h1;
            dst[i] = o;
        }
    }
}

// -------------------------- weight fp32 -> fp16 (w2) -------------------------
__global__ void wconv_kernel(const float4* __restrict__ src, int n4) {
    uint2* __restrict__ dst = (uint2*)g_w2h;
    int i = blockIdx.x * blockDim.x + threadIdx.x;
    int stride = gridDim.x * blockDim.x;
    for (; i < n4; i += stride) {
        float4 v = src[i];
        __half2 h0 = __floats2half2_rn(v.x, v.y);
        __half2 h1 = __floats2half2_rn(v.z, v.w);
        uint2 o; o.x = *(uint32_t*)&h0; o.y = *(uint32_t*)&h1;
        dst[i] = o;
    }
}

// ----------------- WMMA fp16 GEMM, cp.async 4-stage pipeline -----------------
// (round-10 proven config: 128x128x32, 8 warps x 32x64, 2 CTAs/SM)
__device__ __forceinline__ float gelu_exact(float v) {
    return 0.5f * v * (1.f + erff(v * 0.70710678118654752f));
}

template<int KDIM, int NDIM, bool FIRST>
__global__ void __launch_bounds__(256, 2) hgemm(const float* __restrict__ bias) {
    const __half* __restrict__ A  = FIRST ? g_einh : g_hidh;
    const __half* __restrict__ Wh = FIRST ? g_w1h  : g_w2h;
    __half* __restrict__ C        = FIRST ? g_hidh : g_eouth;

    constexpr int BM = 128, BN = 128, BK = 32;
    constexpr int NC = KDIM / BK;
    constexpr int ALD = 40;                       // halves per padded A row
    constexpr int BLD = 136;                      // halves per padded B row
    constexpr int ABYTES = BM * ALD * 2;          // 10240
    constexpr int STAGE  = ABYTES + BK * BLD * 2; // 18944

    extern __shared__ __align__(16) char dsm[];   // 4*STAGE = 75776 B

    const int tid = threadIdx.x, wid = tid >> 5, lane = tid & 31;
    const int bx = blockIdx.x, by = blockIdx.y;
    const int rowBase = by * BM, colBase = bx * BN;
    const int e = rowBase >> 10;
    const __half* __restrict__ Wp = Wh + (size_t)e * KDIM * NDIM;
    const __half* __restrict__ Ap = A + (size_t)rowBase * KDIM;
    const uint32_t sbase = s2u(dsm);
    const int wm = (wid & 3) * 32, wn = (wid >> 2) * 64;

    wmma::fragment<wmma::accumulator, 16, 16, 16, float> acc[2][4];
    #pragma unroll
    for (int i = 0; i < 2; i++)
        #pragma unroll
        for (int j = 0; j < 4; j++) wmma::fill_fragment(acc[i][j], 0.f);

    auto issue = [&](int s, int c) {
        uint32_t ab = sbase + s * STAGE;
        #pragma unroll
        for (int i = 0; i < 2; i++) {
            int ch = tid + i * 256;               // 512 chunks: 128 rows x 64B
            int r = ch >> 2, q = ch & 3;
            CP16(ab + r * 80 + q * 16, Ap + (size_t)r * KDIM + c * BK + q * 8);
        }
        uint32_t bb = sbase + s * STAGE + ABYTES;
        #pragma unroll
        for (int i = 0; i < 2; i++) {
            int ch = tid + i * 256;               // 512 chunks: 32 rows x 256B
            int r = ch >> 4, q = ch & 15;
            CP16(bb + r * 272 + q * 16,
                 Wp + (size_t)(c * BK + r) * NDIM + colBase + q * 8);
        }
    };

    #pragma unroll
    for (int s = 0; s < 3; s++) { issue(s, s); CP_COMMIT(); }

    for (int c = 0; c < NC; c++) {
        CP_WAIT2();
        __syncthreads();
        if (c + 3 < NC) issue((c + 3) & 3, c + 3);
        CP_COMMIT();                              // empty group at tail keeps count

        const __half* As_ = (const __half*)(dsm + (c & 3) * STAGE);
        const __half* Bs_ = (const __half*)(dsm + (c & 3) * STAGE + ABYTES);
        #pragma unroll
        for (int kk = 0; kk < 2; kk++) {
            wmma::fragment<wmma::matrix_a, 16, 16, 16, half, wmma::row_major> af[2];
            wmma::fragment<wmma::matrix_b, 16, 16, 16, half, wmma::row_major> bf[4];
            wmma::load_matrix_sync(af[0], As_ + (wm     ) * ALD + kk * 16, ALD);
            wmma::load_matrix_sync(af[1], As_ + (wm + 16) * ALD + kk * 16, ALD);
            #pragma unroll
            for (int j = 0; j < 4; j++)
                wmma::load_matrix_sync(bf[j], Bs_ + (kk * 16) * BLD + wn + j * 16, BLD);
            #pragma unroll
            for (int i = 0; i < 2; i++)
                #pragma unroll
                for (int j = 0; j < 4; j++)
                    wmma::mma_sync(acc[i][j], af[i], bf[j], acc[i][j]);
        }
        __syncthreads();
    }

    // ---- epilogue: restage 16x64 per warp in smem, fp16 vectorized stores ----
    float* epi = (float*)dsm + wid * 16 * 68;     // 16 rows x ldm 68
    #pragma unroll
    for (int i = 0; i < 2; i++) {
        #pragma unroll
        for (int j = 0; j < 4; j++)
            wmma::store_matrix_sync(epi + j * 16, acc[i][j], 68, wmma::mem_row_major);
        __syncwarp();
        int r0 = rowBase + wm + i * 16;
        int c0 = colBase + wn;
        #pragma unroll
        for (int q = 0; q < 4; q++) {
            int sid = q * 32 + lane;
            int row = sid >> 3, c8 = (sid & 7) * 8;
            float4 b0 = *(const float4*)(&bias[c0 + c8]);
            float4 b1 = *(const float4*)(&bias[c0 + c8 + 4]);
            const float* er = epi + row * 68 + c8;
            float v0 = er[0] + b0.x, v1 = er[1] + b0.y;
            float v2 = er[2] + b0.z, v3 = er[3] + b0.w;
            float v4 = er[4] + b1.x, v5 = er[5] + b1.y;
            float v6 = er[6] + b1.z, v7 = er[7] + b1.w;
            if (FIRST) {
                v0 = gelu_exact(v0); v1 = gelu_exact(v1);
                v2 = gelu_exact(v2); v3 = gelu_exact(v3);
                v4 = gelu_exact(v4); v5 = gelu_exact(v5);
                v6 = gelu_exact(v6); v7 = gelu_exact(v7);
            }
            __half2 h0 = __floats2half2_rn(v0, v1), h1 = __floats2half2_rn(v2, v3);
            __half2 h2 = __floats2half2_rn(v4, v5), h3 = __floats2half2_rn(v6, v7);
            uint4 o; o.x = *(uint32_t*)&h0; o.y = *(uint32_t*)&h1;
            o.z = *(uint32_t*)&h2; o.w = *(uint32_t*)&h3;
            *(uint4*)(&C[(size_t)(r0 + row) * NDIM + c0 + c8]) = o;
        }
        __syncwarp();
    }
}

// ------------------------------- combine (fp16 eout) -------------------------
__global__ void combine_kernel(float* __restrict__ out) {
    int tok = blockIdx.x;
    int t   = threadIdx.x;                         // 256 threads x 4 floats
    int s1 = g_slot1[tok], s2 = g_slot2[tok];
    float g1 = (s1 >= 0) ? g_g1[tok] : 0.f;
    float g2 = (s2 >= 0) ? g_g2[tok] : 0.f;
    float4 v = make_float4(0.f, 0.f, 0.f, 0.f);
    if (s1 >= 0) {
        uint2 raw = ((const uint2*)(g_eouth + (size_t)s1 * DIMM))[t];
        float2 a0 = __half22float2(*(__half2*)&raw.x);
        float2 a1 = __half22float2(*(__half2*)&raw.y);
        v.x += g1 * a0.x; v.y += g1 * a0.y; v.z += g1 * a1.x; v.w += g1 * a1.y;
    }
    if (s2 >= 0) {
        uint2 raw = ((const uint2*)(g_eouth + (size_t)s2 * DIMM))[t];
        float2 a0 = __half22float2(*(__half2*)&raw.x);
        float2 a1 = __half22float2(*(__half2*)&raw.y);
        v.x += g2 * a0.x; v.y += g2 * a0.y; v.z += g2 * a1.x; v.w += g2 * a1.y;
    }
    ((float4*)(out + (size_t)tok * DIMM))[t] = v;
}

// -------------------------------- loss ---------------------------------------
__global__ void loss_part_kernel() {
    int be = blockIdx.x;
    int b = be / NE, e = be % NE;
    __shared__ float s[256];
    float acc = 0.f;
    for (int n = threadIdx.x; n < NN; n += 256)
        acc += g_probs[(size_t)(b * NN + n) * NE + e];
    s[threadIdx.x] = acc; __syncthreads();
    for (int off = 128; off; off >>= 1) {
        if (threadIdx.x < off) s[threadIdx.x] += s[threadIdx.x + off];
        __syncthreads();
    }
    if (threadIdx.x == 0)
        g_part_loss[be] = (s[0] / (float)NN) *
                          ((float)g_cnt_total[be] / (float)NN);
}

__global__ void loss_final_kernel(float* __restrict__ out) {
    __shared__ float s[64];
    int t = threadIdx.x;
    s[t] = g_part_loss[t]; __syncthreads();
    for (int off = 32; off; off >>= 1) {
        if (t < off) s[t] += s[t + off];
        __syncthreads();
    }
    if (t == 0) out[(size_t)NTOK * DIMM] = s[0] * 0.04f;
}

// ------------------------------- launch --------------------------------------
extern "C" void kernel_launch(void* const* d_in, const int* in_sizes, int n_in,
                              void* d_out, int out_size) {
    const float* x  = (const float*)d_in[0];
    const float* wg = (const float*)d_in[1];
    const float* w1 = (const float*)d_in[2];
    const float* w2 = (const float*)d_in[3];
    const float* b1 = (const float*)d_in[4];
    const float* b2 = (const float*)d_in[5];
    float* out = (float*)d_out;

    constexpr int SMEM = 4 * 18944;   // 75776
    cudaFuncSetAttribute(hgemm<DIMM, HID,  true >,
                         cudaFuncAttributeMaxDynamicSharedMemorySize, SMEM);
    cudaFuncSetAttribute(hgemm<HID,  DIMM, false>,
                         cudaFuncAttributeMaxDynamicSharedMemorySize, SMEM);

    const int W4 = NE * DIMM * HID / 4;
    gating_kernel<<<NTOK, 512>>>(x, wg);                                  // 0
    assign_kernel<<<BB * NE, 256>>>();                                    // 1
    gather_wconv1_kernel<<<NSLOT + 8192, 256>>>(x, (const float4*)w1, W4);// 2
    hgemm<DIMM, HID,  true ><<<dim3(HID / 128, NSLOT / 128), 256, SMEM>>>(b1); // 3
    wconv_kernel<<<8192, 256>>>((const float4*)w2, W4);                   // 4
    hgemm<HID,  DIMM, false><<<dim3(DIMM / 128, NSLOT / 128), 256, SMEM>>>(b2); // 5
    combine_kernel<<<NTOK, 256>>>(out);                                   // 6
    loss_part_kernel<<<BB * NE, 256>>>();                                 // 7
    if (out_size > NTOK * DIMM)
        loss_final_kernel<<<1, 64>>>(out);                                // 8
}

// round 14
// speedup vs baseline: 1.1337x; 1.0318x over previous
#include <cuda_runtime.h>
#include <cuda_fp16.h>
#include <mma.h>
#include <math.h>
#include <stdint.h>

#define BB   4
#define NN   2048
#define DIMM 1024
#define HID  4096
#define NE   16
#define CAP  256
#define NTOK (BB*NN)          // 8192 tokens
#define NSLOT (NE*BB*CAP)     // 16384 expert slot rows
#define FLT_MIN_NORM 1.17549435e-38f
#define EXP_FTZ_CUT  (-87.336544f)

using namespace nvcuda;

// ------------------------- scratch (device globals) -------------------------
__device__ float  g_probs[NTOK*NE];
__device__ int    g_e1[NTOK], g_e2[NTOK];
__device__ float  g_g1[NTOK], g_g2[NTOK];
__device__ int    g_slot1[NTOK], g_slot2[NTOK];
__device__ int    g_slot_token[NSLOT];
__device__ int    g_cnt_total[BB*NE];
__device__ float  g_part_loss[BB*NE];
__device__ __half g_einh [(size_t)NSLOT*DIMM];       // 32 MB
__device__ __half g_hidh [(size_t)NSLOT*HID];        // 128 MB
__device__ __half g_eouth[(size_t)NSLOT*DIMM];       // 32 MB
__device__ __half g_w1h  [(size_t)NE*DIMM*HID];      // 128 MB
__device__ __half g_w2h  [(size_t)NE*HID*DIMM];      // 128 MB

// ------------------------- async-copy helpers --------------------------------
__device__ __forceinline__ uint32_t s2u(const void* p) {
    uint32_t a;
    asm("{ .reg .u64 t; cvta.to.shared.u64 t, %1; cvt.u32.u64 %0, t; }"
        : "=r"(a) : "l"(p));
    return a;
}
#define CP16(dst, src) \
    asm volatile("cp.async.cg.shared.global [%0], [%1], 16;" \
                 :: "r"(dst), "l"(src) : "memory")
#define CP_COMMIT() asm volatile("cp.async.commit_group;" ::: "memory")
#define CP_WAIT1()  asm volatile("cp.async.wait_group 1;" ::: "memory")

// ------------------------------ gating ---------------------------------------
// Logits via warp-tree reduction (routing invariant to summation order, proven
// rounds 1/3/4). FTZ softmax / argmax / gates_wo1 pipeline is GOLDEN.
__global__ void gating_kernel(const float* __restrict__ x,
                              const float* __restrict__ wg) {
    int tok  = blockIdx.x;
    int wid  = threadIdx.x >> 5;        // expert
    int lane = threadIdx.x & 31;
    const float* xr = x + (size_t)tok * DIMM;

    float acc = 0.f;
    #pragma unroll 8
    for (int d = lane; d < DIMM; d += 32)
        acc = fmaf(xr[d], wg[d * NE + wid], acc);
    #pragma unroll
    for (int o = 16; o; o >>= 1) acc += __shfl_xor_sync(0xffffffffu, acc, o);

    __shared__ float lg[NE];
    if (lane == 0) lg[wid] = acc;
    __syncthreads();

    if (threadIdx.x == 0) {
        float l[NE], p[NE];
        #pragma unroll
        for (int i = 0; i < NE; i++) l[i] = lg[i];

        float m = l[0];
        #pragma unroll
        for (int i = 1; i < NE; i++) m = fmaxf(m, l[i]);
        float s = 0.f;
        #pragma unroll
        for (int i = 0; i < NE; i++) {
            float t = l[i] - m;
            float pe = (t < EXP_FTZ_CUT) ? 0.f : expf(t);   // FTZ exp
            p[i] = pe; s = s + pe;
        }
        #pragma unroll
        for (int i = 0; i < NE; i++) {
            float q = p[i] / s;
            if (q < FLT_MIN_NORM) q = 0.f;                  // FTZ divide
            p[i] = q;
        }

        int i1 = 0; float p1 = p[0];
        #pragma unroll
        for (int i = 1; i < NE; i++) if (p[i] > p1) { p1 = p[i]; i1 = i; }
        float gw[NE];
        #pragma unroll
        for (int i = 0; i < NE; i++) gw[i] = (i == i1) ? 0.f : p[i];
        int i2 = 0; float p2v = gw[0];
        #pragma unroll
        for (int i = 1; i < NE; i++) if (gw[i] > p2v) { p2v = gw[i]; i2 = i; }

        float den = p1 + p2v + 1e-9f;
        g_e1[tok] = i1; g_e2[tok] = i2;
        g_g1[tok] = p1 / den; g_g2[tok] = p2v / den;
        #pragma unroll
        for (int i = 0; i < NE; i++) g_probs[tok * NE + i] = p[i];
    }
}

// ---------------- capacity / assign (slot-segment clear fused in) ------------
__global__ void assign_kernel() {
    const int T = 256, TPT = NN / T;
    int b = blockIdx.x / NE, e = blockIdx.x % NE;
    int t = threadIdx.x;
    __shared__ int s[T];

    g_slot_token[(e * BB + b) * CAP + t] = -1;
    __syncthreads();

    int flag[TPT], loc[TPT]; int c = 0;
    #pragma unroll
    for (int i = 0; i < TPT; i++) {
        int n = t * TPT + i;
        int f = (g_e1[b * NN + n] == e);
        flag[i] = f; loc[i] = c; c += f;
    }
    s[t] = c; __syncthreads();
    for (int off = 1; off < T; off <<= 1) {
        int v = (t >= off) ? s[t - off] : 0;
        __syncthreads(); s[t] += v; __syncthreads();
    }
    int total = s[T - 1];
    int excl  = s[t] - c;
    #pragma unroll
    for (int i = 0; i < TPT; i++) {
        if (flag[i]) {
            int n = t * TPT + i, gi = b * NN + n;
            int pos = excl + loc[i];
            if (pos < CAP) {
                int slot = (e * BB + b) * CAP + pos;
                g_slot1[gi] = slot;
                g_slot_token[slot] = gi;
            } else g_slot1[gi] = -1;
        }
    }
    if (t == 0) g_cnt_total[b * NE + e] = total;
    int kept1 = total < CAP ? total : CAP;
    __syncthreads();

    c = 0;
    #pragma unroll
    for (int i = 0; i < TPT; i++) {
        int n = t * TPT + i;
        int f = (g_e2[b * NN + n] == e);
        flag[i] = f; loc[i] = c; c += f;
    }
    s[t] = c; __syncthreads();
    for (int off = 1; off < T; off <<= 1) {
        int v = (t >= off) ? s[t - off] : 0;
        __syncthreads(); s[t] += v; __syncthreads();
    }
    excl = s[t] - c;
    #pragma unroll
    for (int i = 0; i < TPT; i++) {
        if (flag[i]) {
            int n = t * TPT + i, gi = b * NN + n;
            int pos = excl + loc[i] + kept1;
            if (pos < CAP) {
                int slot = (e * BB + b) * CAP + pos;
                g_slot2[gi] = slot;
                g_slot_token[slot] = gi;
            } else g_slot2[gi] = -1;
        }
    }
}

// --------- gather (fp32 -> fp16) + w1 + w2 conversion, all fused -------------
// blocks [0, NSLOT)                  : gather token rows into g_einh
// blocks [NSLOT, NSLOT+8192)         : convert w1 -> g_w1h (grid-stride)
// blocks [NSLOT+8192, NSLOT+16384)   : convert w2 -> g_w2h (grid-stride)
__global__ void gather_wconv_kernel(const float* __restrict__ x,
                                    const float4* __restrict__ w1src,
                                    const float4* __restrict__ w2src, int n4) {
    if (blockIdx.x < NSLOT) {
        int row = blockIdx.x;
        int tok = g_slot_token[row];
        uint2* dst = (uint2*)(g_einh + (size_t)row * DIMM);
        int t = threadIdx.x;
        if (tok >= 0) {
            float4 v = ((const float4*)(x + (size_t)tok * DIMM))[t];
            __half2 h0 = __floats2half2_rn(v.x, v.y);
            __half2 h1 = __floats2half2_rn(v.z, v.w);
            uint2 o; o.x = *(uint32_t*)&h0; o.y = *(uint32_t*)&h1;
            dst[t] = o;
        } else {
            dst[t] = make_uint2(0u, 0u);
        }
    } else {
        int wsel = (blockIdx.x - NSLOT) >> 13;            // 0: w1, 1: w2
        const float4* __restrict__ src = wsel ? w2src : w1src;
        uint2* __restrict__ dst = wsel ? (uint2*)g_w2h : (uint2*)g_w1h;
        int i = ((blockIdx.x - NSLOT) & 8191) * blockDim.x + threadIdx.x;
        int stride = 8192 * blockDim.x;
        for (; i < n4; i += stride) {
            float4 v = src[i];
            __half2 h0 = __floats2half2_rn(v.x, v.y);
            __half2 h1 = __floats2half2_rn(v.z, v.w);
            uint2 o; o.x = *(uint32_t*)&h0; o.y = *(uint32_t*)&h1;
            dst[i] = o;
        }
    }
}

// ----------------- WMMA fp16 GEMM, BK=64, 3-stage cp.async -------------------
// 128x128x64 tile, 8 warps x 32x64 warp tile, 2 CTAs/SM.
__device__ __forceinline__ float gelu_exact(float v) {
    return 0.5f * v * (1.f + erff(v * 0.70710678118654752f));
}

template<int KDIM, int NDIM, bool FIRST>
__global__ void __launch_bounds__(256, 2) hgemm(const float* __restrict__ bias) {
    const __half* __restrict__ A  = FIRST ? g_einh : g_hidh;
    const __half* __restrict__ Wh = FIRST ? g_w1h  : g_w2h;
    __half* __restrict__ C        = FIRST ? g_hidh : g_eouth;

    constexpr int BM = 128, BN = 128, BK = 64;
    constexpr int NC = KDIM / BK;
    constexpr int ALD = 72;                       // halves per padded A row
    constexpr int BLD = 136;                      // halves per padded B row
    constexpr int ABYTES = BM * ALD * 2;          // 18432
    constexpr int STAGE  = ABYTES + BK * BLD * 2; // 35840
    constexpr int NSTG   = 3;                     // 107520 B smem

    extern __shared__ __align__(16) char dsm[];

    const int tid = threadIdx.x, wid = tid >> 5, lane = tid & 31;
    const int bx = blockIdx.x, by = blockIdx.y;
    const int rowBase = by * BM, colBase = bx * BN;
    const int e = rowBase >> 10;
    const __half* __restrict__ Wp = Wh + (size_t)e * KDIM * NDIM;
    const __half* __restrict__ Ap = A + (size_t)rowBase * KDIM;
    const uint32_t sbase = s2u(dsm);
    const int wm = (wid & 3) * 32, wn = (wid >> 2) * 64;

    wmma::fragment<wmma::accumulator, 16, 16, 16, float> acc[2][4];
    #pragma unroll
    for (int i = 0; i < 2; i++)
        #pragma unroll
        for (int j = 0; j < 4; j++) wmma::fill_fragment(acc[i][j], 0.f);

    // per-thread copy coordinates (hoisted out of the loop)
    const int a_r = tid >> 1;                     // with 4 iters: rows tid>>1 + ...
    const int b_rbase = tid >> 4, b_q = tid & 15;

    auto issue = [&](int s, int c) {
        uint32_t ab = sbase + s * STAGE;
        const __half* asrc = Ap + (size_t)0 * KDIM + c * BK;
        // A: 128 rows x 128B = 1024 chunks of 16B; 256 thr x 4
        #pragma unroll
        for (int i = 0; i < 4; i++) {
            int ch = tid + i * 256;
            int r = ch >> 3, q = ch & 7;
            CP16(ab + r * 144 + q * 16, asrc + (size_t)r * KDIM + q * 8);
        }
        uint32_t bb = sbase + s * STAGE + ABYTES;
        const __half* bsrc = Wp + (size_t)(c * BK) * NDIM + colBase;
        // B: 64 rows x 256B = 1024 chunks of 16B; 256 thr x 4
        #pragma unroll
        for (int i = 0; i < 4; i++) {
            int ch = tid + i * 256;
            int r = ch >> 4, q = ch & 15;
            CP16(bb + r * 272 + q * 16, bsrc + (size_t)r * NDIM + q * 8);
        }
    };

    issue(0, 0); CP_COMMIT();
    issue(1, 1); CP_COMMIT();

    for (int c = 0; c < NC; c++) {
        int stg = c % NSTG;
        CP_WAIT1();
        __syncthreads();
        if (c + 2 < NC) issue((c + 2) % NSTG, c + 2);
        CP_COMMIT();                              // keeps group count aligned

        const __half* As_ = (const __half*)(dsm + stg * STAGE);
        const __half* Bs_ = (const __half*)(dsm + stg * STAGE + ABYTES);
        #pragma unroll
        for (int kk = 0; kk < 4; kk++) {
            wmma::fragment<wmma::matrix_a, 16, 16, 16, half, wmma::row_major> af[2];
            wmma::fragment<wmma::matrix_b, 16, 16, 16, half, wmma::row_major> bf[4];
            wmma::load_matrix_sync(af[0], As_ + (wm     ) * ALD + kk * 16, ALD);
            wmma::load_matrix_sync(af[1], As_ + (wm + 16) * ALD + kk * 16, ALD);
            #pragma unroll
            for (int j = 0; j < 4; j++)
                wmma::load_matrix_sync(bf[j], Bs_ + (kk * 16) * BLD + wn + j * 16, BLD);
            #pragma unroll
            for (int i = 0; i < 2; i++)
                #pragma unroll
                for (int j = 0; j < 4; j++)
                    wmma::mma_sync(acc[i][j], af[i], bf[j], acc[i][j]);
        }
        __syncthreads();
    }

    // ---- epilogue: restage 16x64 per warp in smem, fp16 vectorized stores ----
    float* epi = (float*)dsm + wid * 16 * 68;     // 16 rows x ldm 68
    #pragma unroll
    for (int i = 0; i < 2; i++) {
        #pragma unroll
        for (int j = 0; j < 4; j++)
            wmma::store_matrix_sync(epi + j * 16, acc[i][j], 68, wmma::mem_row_major);
        __syncwarp();
        int r0 = rowBase + wm + i * 16;
        int c0 = colBase + wn;
        #pragma unroll
        for (int q = 0; q < 4; q++) {
            int sid = q * 32 + lane;
            int row = sid >> 3, c8 = (sid & 7) * 8;
            float4 b0 = *(const float4*)(&bias[c0 + c8]);
            float4 b1 = *(const float4*)(&bias[c0 + c8 + 4]);
            const float* er = epi + row * 68 + c8;
            float v0 = er[0] + b0.x, v1 = er[1] + b0.y;
            float v2 = er[2] + b0.z, v3 = er[3] + b0.w;
            float v4 = er[4] + b1.x, v5 = er[5] + b1.y;
            float v6 = er[6] + b1.z, v7 = er[7] + b1.w;
            if (FIRST) {
                v0 = gelu_exact(v0); v1 = gelu_exact(v1);
                v2 = gelu_exact(v2); v3 = gelu_exact(v3);
                v4 = gelu_exact(v4); v5 = gelu_exact(v5);
                v6 = gelu_exact(v6); v7 = gelu_exact(v7);
            }
            __half2 h0 = __floats2half2_rn(v0, v1), h1 = __floats2half2_rn(v2, v3);
            __half2 h2 = __floats2half2_rn(v4, v5), h3 = __floats2half2_rn(v6, v7);
            uint4 o; o.x = *(uint32_t*)&h0; o.y = *(uint32_t*)&h1;
            o.z = *(uint32_t*)&h2; o.w = *(uint32_t*)&h3;
            *(uint4*)(&C[(size_t)(r0 + row) * NDIM + c0 + c8]) = o;
        }
        __syncwarp();
    }
}

// ------------------------------- combine (fp16 eout) -------------------------
__global__ void combine_kernel(float* __restrict__ out) {
    int tok = blockIdx.x;
    int t   = threadIdx.x;
    int s1 = g_slot1[tok], s2 = g_slot2[tok];
    float g1 = (s1 >= 0) ? g_g1[tok] : 0.f;
    float g2 = (s2 >= 0) ? g_g2[tok] : 0.f;
    float4 v = make_float4(0.f, 0.f, 0.f, 0.f);
    if (s1 >= 0) {
        uint2 raw = ((const uint2*)(g_eouth + (size_t)s1 * DIMM))[t];
        float2 a0 = __half22float2(*(__half2*)&raw.x);
        float2 a1 = __half22float2(*(__half2*)&raw.y);
        v.x += g1 * a0.x; v.y += g1 * a0.y; v.z += g1 * a1.x; v.w += g1 * a1.y;
    }
    if (s2 >= 0) {
        uint2 raw = ((const uint2*)(g_eouth + (size_t)s2 * DIMM))[t];
        float2 a0 = __half22float2(*(__half2*)&raw.x);
        float2 a1 = __half22float2(*(__half2*)&raw.y);
        v.x += g2 * a0.x; v.y += g2 * a0.y; v.z += g2 * a1.x; v.w += g2 * a1.y;
    }
    ((float4*)(out + (size_t)tok * DIMM))[t] = v;
}

// -------------------------------- loss ---------------------------------------
__global__ void loss_part_kernel() {
    int be = blockIdx.x;
    int b = be / NE, e = be % NE;
    __shared__ float s[256];
    float acc = 0.f;
    for (int n = threadIdx.x; n < NN; n += 256)
        acc += g_probs[(size_t)(b * NN + n) * NE + e];
    s[threadIdx.x] = acc; __syncthreads();
    for (int off = 128; off; off >>= 1) {
        if (threadIdx.x < off) s[threadIdx.x] += s[threadIdx.x + off];
        __syncthreads();
    }
    if (threadIdx.x == 0)
        g_part_loss[be] = (s[0] / (float)NN) *
                          ((float)g_cnt_total[be] / (float)NN);
}

__global__ void loss_final_kernel(float* __restrict__ out) {
    __shared__ float s[64];
    int t = threadIdx.x;
    s[t] = g_part_loss[t]; __syncthreads();
    for (int off = 32; off; off >>= 1) {
        if (t < off) s[t] += s[t + off];
        __syncthreads();
    }
    if (t == 0) out[(size_t)NTOK * DIMM] = s[0] * 0.04f;
}

// ------------------------------- launch --------------------------------------
extern "C" void kernel_launch(void* const* d_in, const int* in_sizes, int n_in,
                              void* d_out, int out_size) {
    const float* x  = (const float*)d_in[0];
    const float* wg = (const float*)d_in[1];
    const float* w1 = (const float*)d_in[2];
    const float* w2 = (const float*)d_in[3];
    const float* b1 = (const float*)d_in[4];
    const float* b2 = (const float*)d_in[5];
    float* out = (float*)d_out;

    constexpr int SMEM = 3 * 35840;   // 107520
    cudaFuncSetAttribute(hgemm<DIMM, HID,  true >,
                         cudaFuncAttributeMaxDynamicSharedMemorySize, SMEM);
    cudaFuncSetAttribute(hgemm<HID,  DIMM, false>,
                         cudaFuncAttributeMaxDynamicSharedMemorySize, SMEM);

    const int W4 = NE * DIMM * HID / 4;
    gating_kernel<<<NTOK, 512>>>(x, wg);                                  // 0
    assign_kernel<<<BB * NE, 256>>>();                                    // 1
    gather_wconv_kernel<<<NSLOT + 16384, 256>>>(x, (const float4*)w1,
                                                (const float4*)w2, W4);   // 2
    hgemm<DIMM, HID,  true ><<<dim3(HID / 128, NSLOT / 128), 256, SMEM>>>(b1); // 3
    hgemm<HID,  DIMM, false><<<dim3(DIMM / 128, NSLOT / 128), 256, SMEM>>>(b2); // 4
    combine_kernel<<<NTOK, 256>>>(out);                                   // 5
    loss_part_kernel<<<BB * NE, 256>>>();                                 // 6
    if (out_size > NTOK * DIMM)
        loss_final_kernel<<<1, 64>>>(out);                                // 7
}

// round 15
// speedup vs baseline: 1.1482x; 1.0128x over previous
#include <cuda_runtime.h>
#include <cuda_fp16.h>
#include <mma.h>
#include <math.h>
#include <stdint.h>

#define BB   4
#define NN   2048
#define DIMM 1024
#define HID  4096
#define NE   16
#define CAP  256
#define NTOK (BB*NN)          // 8192 tokens
#define NSLOT (NE*BB*CAP)     // 16384 expert slot rows
#define FLT_MIN_NORM 1.17549435e-38f
#define EXP_FTZ_CUT  (-87.336544f)

using namespace nvcuda;

// ------------------------- scratch (device globals) -------------------------
__device__ float  g_probs[NTOK*NE];
__device__ int    g_e1[NTOK], g_e2[NTOK];
__device__ float  g_g1[NTOK], g_g2[NTOK];
__device__ int    g_slot1[NTOK], g_slot2[NTOK];
__device__ int    g_slot_token[NSLOT];
__device__ int    g_cnt_total[BB*NE];
__device__ float  g_part_loss[BB*NE];
__device__ __half g_einh [(size_t)NSLOT*DIMM];       // 32 MB
__device__ __half g_hidh [(size_t)NSLOT*HID];        // 128 MB
__device__ __half g_eouth[(size_t)NSLOT*DIMM];       // 32 MB
__device__ __half g_w1h  [(size_t)NE*DIMM*HID];      // 128 MB
__device__ __half g_w2h  [(size_t)NE*HID*DIMM];      // 128 MB

// ------------------------- async-copy helpers --------------------------------
__device__ __forceinline__ uint32_t s2u(const void* p) {
    uint32_t a;
    asm("{ .reg .u64 t; cvta.to.shared.u64 t, %1; cvt.u32.u64 %0, t; }"
        : "=r"(a) : "l"(p));
    return a;
}
#define CP16(dst, src) \
    asm volatile("cp.async.cg.shared.global [%0], [%1], 16;" \
                 :: "r"(dst), "l"(src) : "memory")
#define CP_COMMIT() asm volatile("cp.async.commit_group;" ::: "memory")
#define CP_WAIT1()  asm volatile("cp.async.wait_group 1;" ::: "memory")

// ------------------------------ gating ---------------------------------------
// Logits via warp-tree reduction (routing invariant to summation order, proven
// rounds 1/3/4). FTZ softmax / argmax / gates_wo1 pipeline is GOLDEN.
__global__ void gating_kernel(const float* __restrict__ x,
                              const float* __restrict__ wg) {
    int tok  = blockIdx.x;
    int wid  = threadIdx.x >> 5;        // expert
    int lane = threadIdx.x & 31;
    const float* xr = x + (size_t)tok * DIMM;

    float acc = 0.f;
    #pragma unroll 8
    for (int d = lane; d < DIMM; d += 32)
        acc = fmaf(xr[d], wg[d * NE + wid], acc);
    #pragma unroll
    for (int o = 16; o; o >>= 1) acc += __shfl_xor_sync(0xffffffffu, acc, o);

    __shared__ float lg[NE];
    if (lane == 0) lg[wid] = acc;
    __syncthreads();

    if (threadIdx.x == 0) {
        float l[NE], p[NE];
        #pragma unroll
        for (int i = 0; i < NE; i++) l[i] = lg[i];

        float m = l[0];
        #pragma unroll
        for (int i = 1; i < NE; i++) m = fmaxf(m, l[i]);
        float s = 0.f;
        #pragma unroll
        for (int i = 0; i < NE; i++) {
            float t = l[i] - m;
            float pe = (t < EXP_FTZ_CUT) ? 0.f : expf(t);   // FTZ exp
            p[i] = pe; s = s + pe;
        }
        #pragma unroll
        for (int i = 0; i < NE; i++) {
            float q = p[i] / s;
            if (q < FLT_MIN_NORM) q = 0.f;                  // FTZ divide
            p[i] = q;
        }

        int i1 = 0; float p1 = p[0];
        #pragma unroll
        for (int i = 1; i < NE; i++) if (p[i] > p1) { p1 = p[i]; i1 = i; }
        float gw[NE];
        #pragma unroll
        for (int i = 0; i < NE; i++) gw[i] = (i == i1) ? 0.f : p[i];
        int i2 = 0; float p2v = gw[0];
        #pragma unroll
        for (int i = 1; i < NE; i++) if (gw[i] > p2v) { p2v = gw[i]; i2 = i; }

        float den = p1 + p2v + 1e-9f;
        g_e1[tok] = i1; g_e2[tok] = i2;
        g_g1[tok] = p1 / den; g_g2[tok] = p2v / den;
        #pragma unroll
        for (int i = 0; i < NE; i++) g_probs[tok * NE + i] = p[i];
    }
}

// ---------------- capacity / assign (slot-segment clear fused in) ------------
__global__ void assign_kernel() {
    const int T = 256, TPT = NN / T;
    int b = blockIdx.x / NE, e = blockIdx.x % NE;
    int t = threadIdx.x;
    __shared__ int s[T];

    g_slot_token[(e * BB + b) * CAP + t] = -1;
    __syncthreads();

    int flag[TPT], loc[TPT]; int c = 0;
    #pragma unroll
    for (int i = 0; i < TPT; i++) {
        int n = t * TPT + i;
        int f = (g_e1[b * NN + n] == e);
        flag[i] = f; loc[i] = c; c += f;
    }
    s[t] = c; __syncthreads();
    for (int off = 1; off < T; off <<= 1) {
        int v = (t >= off) ? s[t - off] : 0;
        __syncthreads(); s[t] += v; __syncthreads();
    }
    int total = s[T - 1];
    int excl  = s[t] - c;
    #pragma unroll
    for (int i = 0; i < TPT; i++) {
        if (flag[i]) {
            int n = t * TPT + i, gi = b * NN + n;
            int pos = excl + loc[i];
            if (pos < CAP) {
                int slot = (e * BB + b) * CAP + pos;
                g_slot1[gi] = slot;
                g_slot_token[slot] = gi;
            } else g_slot1[gi] = -1;
        }
    }
    if (t == 0) g_cnt_total[b * NE + e] = total;
    int kept1 = total < CAP ? total : CAP;
    __syncthreads();

    c = 0;
    #pragma unroll
    for (int i = 0; i < TPT; i++) {
        int n = t * TPT + i;
        int f = (g_e2[b * NN + n] == e);
        flag[i] = f; loc[i] = c; c += f;
    }
    s[t] = c; __syncthreads();
    for (int off = 1; off < T; off <<= 1) {
        int v = (t >= off) ? s[t - off] : 0;
        __syncthreads(); s[t] += v; __syncthreads();
    }
    excl = s[t] - c;
    #pragma unroll
    for (int i = 0; i < TPT; i++) {
        if (flag[i]) {
            int n = t * TPT + i, gi = b * NN + n;
            int pos = excl + loc[i] + kept1;
            if (pos < CAP) {
                int slot = (e * BB + b) * CAP + pos;
                g_slot2[gi] = slot;
                g_slot_token[slot] = gi;
            } else g_slot2[gi] = -1;
        }
    }
}

// --------- gather (fp32 -> fp16) + w1 conversion, fused ----------------------
__global__ void gather_wconv1_kernel(const float* __restrict__ x,
                                     const float4* __restrict__ w1src, int n4) {
    if (blockIdx.x < NSLOT) {
        int row = blockIdx.x;
        int tok = g_slot_token[row];
        uint2* dst = (uint2*)(g_einh + (size_t)row * DIMM);
        int t = threadIdx.x;
        if (tok >= 0) {
            float4 v = ((const float4*)(x + (size_t)tok * DIMM))[t];
            __half2 h0 = __floats2half2_rn(v.x, v.y);
            __half2 h1 = __floats2half2_rn(v.z, v.w);
            uint2 o; o.x = *(uint32_t*)&h0; o.y = *(uint32_t*)&h1;
            dst[t] = o;
        } else {
            dst[t] = make_uint2(0u, 0u);
        }
    } else {
        uint2* __restrict__ dst = (uint2*)g_w1h;
        int i = (blockIdx.x - NSLOT) * blockDim.x + threadIdx.x;
        int stride = 8192 * blockDim.x;
        for (; i < n4; i += stride) {
            float4 v = w1src[i];
            __half2 h0 = __floats2half2_rn(v.x, v.y);
            __half2 h1 = __floats2half2_rn(v.z, v.w);
            uint2 o; o.x = *(uint32_t*)&h0; o.y = *(uint32_t*)&h1;
            dst[i] = o;
        }
    }
}

// ----------------- WMMA fp16 GEMM, BK=64, 3-stage, 1 sync/chunk --------------
// 128x128x64 tile, 8 warps x 32x64 warp tile, 2 CTAs/SM.
// FIRST variant carries wconv2 in extra blocks (overlaps w2 conversion).
__device__ __forceinline__ float gelu_exact(float v) {
    return 0.5f * v * (1.f + erff(v * 0.70710678118654752f));
}

template<int KDIM, int NDIM, bool FIRST>
__global__ void __launch_bounds__(256, 2) hgemm(const float* __restrict__ bias,
                                                const float4* __restrict__ w2src,
                                                int n4) {
    constexpr int GRIDX = NDIM / 128;
    constexpr int NGEMM = GRIDX * (NSLOT / 128);

    if (FIRST && blockIdx.x >= NGEMM) {
        // ---- fused wconv2: convert w2 fp32 -> fp16 while GEMM1 runs ----
        uint2* __restrict__ dst = (uint2*)g_w2h;
        int i = (blockIdx.x - NGEMM) * blockDim.x + threadIdx.x;
        int stride = 2048 * blockDim.x;
        for (; i < n4; i += stride) {
            float4 v = w2src[i];
            __half2 h0 = __floats2half2_rn(v.x, v.y);
            __half2 h1 = __floats2half2_rn(v.z, v.w);
            uint2 o; o.x = *(uint32_t*)&h0; o.y = *(uint32_t*)&h1;
            dst[i] = o;
        }
        return;
    }

    const __half* __restrict__ A  = FIRST ? g_einh : g_hidh;
    const __half* __restrict__ Wh = FIRST ? g_w1h  : g_w2h;
    __half* __restrict__ C        = FIRST ? g_hidh : g_eouth;

    constexpr int BM = 128, BK = 64;
    constexpr int NC = KDIM / BK;
    constexpr int ALD = 72;                       // halves per padded A row
    constexpr int BLD = 136;                      // halves per padded B row
    constexpr int ABYTES = BM * ALD * 2;          // 18432
    constexpr int STAGE  = ABYTES + BK * BLD * 2; // 35840

    extern __shared__ __align__(16) char dsm[];   // 3*STAGE = 107520 B

    const int tid = threadIdx.x, wid = tid >> 5, lane = tid & 31;
    const int bx = blockIdx.x % GRIDX, by = blockIdx.x / GRIDX;
    const int rowBase = by * BM, colBase = bx * 128;
    const int e = rowBase >> 10;
    const uint32_t sbase = s2u(dsm);
    const int wm = (wid & 3) * 32, wn = (wid >> 2) * 64;

    // ---- hoisted per-thread copy coordinates ----
    // A: 4 chunks of 16B; ch = tid + i*256 -> r = ch>>3, q = ch&7
    // B: 4 chunks of 16B; ch = tid + i*256 -> r = ch>>4, q = ch&15
    uint32_t a_soff[4], b_soff[4];
    const __half* a_gp[4];
    const __half* b_gp[4];
    {
        const __half* Ap = A + (size_t)rowBase * KDIM;
        const __half* Bp = Wh + (size_t)e * KDIM * NDIM + colBase;
        #pragma unroll
        for (int i = 0; i < 4; i++) {
            int ch = tid + i * 256;
            int ar = ch >> 3, aq = ch & 7;
            a_soff[i] = ar * 144 + aq * 16;
            a_gp[i]   = Ap + (size_t)ar * KDIM + aq * 8;
            int br = ch >> 4, bq = ch & 15;
            b_soff[i] = ABYTES + br * 272 + bq * 16;
            b_gp[i]   = Bp + (size_t)br * NDIM + bq * 8;
        }
    }

    wmma::fragment<wmma::accumulator, 16, 16, 16, float> acc[2][4];
    #pragma unroll
    for (int i = 0; i < 2; i++)
        #pragma unroll
        for (int j = 0; j < 4; j++) wmma::fill_fragment(acc[i][j], 0.f);

    auto issue = [&](int s) {
        uint32_t sb = sbase + s * STAGE;
        #pragma unroll
        for (int i = 0; i < 4; i++) CP16(sb + a_soff[i], a_gp[i]);
        #pragma unroll
        for (int i = 0; i < 4; i++) CP16(sb + b_soff[i], b_gp[i]);
        #pragma unroll
        for (int i = 0; i < 4; i++) { a_gp[i] += BK; b_gp[i] += (size_t)BK * NDIM; }
    };

    issue(0); CP_COMMIT();
    issue(1); CP_COMMIT();

    for (int c = 0; c < NC; c++) {
        int stg = c % 3;
        CP_WAIT1();
        __syncthreads();                          // single barrier per chunk
        if (c + 2 < NC) issue((c + 2) % 3);
        CP_COMMIT();

        const __half* As_ = (const __half*)(dsm + stg * STAGE);
        const __half* Bs_ = (const __half*)(dsm + stg * STAGE + ABYTES);
        #pragma unroll
        for (int kk = 0; kk < 4; kk++) {
            wmma::fragment<wmma::matrix_a, 16, 16, 16, half, wmma::row_major> af[2];
            wmma::fragment<wmma::matrix_b, 16, 16, 16, half, wmma::row_major> bf[4];
            wmma::load_matrix_sync(af[0], As_ + (wm     ) * ALD + kk * 16, ALD);
            wmma::load_matrix_sync(af[1], As_ + (wm + 16) * ALD + kk * 16, ALD);
            #pragma unroll
            for (int j = 0; j < 4; j++)
                wmma::load_matrix_sync(bf[j], Bs_ + (kk * 16) * BLD + wn + j * 16, BLD);
            #pragma unroll
            for (int i = 0; i < 2; i++)
                #pragma unroll
                for (int j = 0; j < 4; j++)
                    wmma::mma_sync(acc[i][j], af[i], bf[j], acc[i][j]);
        }
    }
    __syncthreads();                              // all compute done before epi reuse

    // ---- epilogue: restage 16x64 per warp in smem, fp16 vectorized stores ----
    float* epi = (float*)dsm + wid * 16 * 68;     // 16 rows x ldm 68
    #pragma unroll
    for (int i = 0; i < 2; i++) {
        #pragma unroll
        for (int j = 0; j < 4; j++)
            wmma::store_matrix_sync(epi + j * 16, acc[i][j], 68, wmma::mem_row_major);
        __syncwarp();
        int r0 = rowBase + wm + i * 16;
        int c0 = colBase + wn;
        #pragma unroll
        for (int q = 0; q < 4; q++) {
            int sid = q * 32 + lane;
            int row = sid >> 3, c8 = (sid & 7) * 8;
            float4 b0 = *(const float4*)(&bias[c0 + c8]);
            float4 b1 = *(const float4*)(&bias[c0 + c8 + 4]);
            const float* er = epi + row * 68 + c8;
            float v0 = er[0] + b0.x, v1 = er[1] + b0.y;
            float v2 = er[2] + b0.z, v3 = er[3] + b0.w;
            float v4 = er[4] + b1.x, v5 = er[5] + b1.y;
            float v6 = er[6] + b1.z, v7 = er[7] + b1.w;
            if (FIRST) {
                v0 = gelu_exact(v0); v1 = gelu_exact(v1);
                v2 = gelu_exact(v2); v3 = gelu_exact(v3);
                v4 = gelu_exact(v4); v5 = gelu_exact(v5);
                v6 = gelu_exact(v6); v7 = gelu_exact(v7);
            }
            __half2 h0 = __floats2half2_rn(v0, v1), h1 = __floats2half2_rn(v2, v3);
            __half2 h2 = __floats2half2_rn(v4, v5), h3 = __floats2half2_rn(v6, v7);
            uint4 o; o.x = *(uint32_t*)&h0; o.y = *(uint32_t*)&h1;
            o.z = *(uint32_t*)&h2; o.w = *(uint32_t*)&h3;
            *(uint4*)(&C[(size_t)(r0 + row) * NDIM + c0 + c8]) = o;
        }
        __syncwarp();
    }
}

// ------------------------------- combine (fp16 eout) -------------------------
__global__ void combine_kernel(float* __restrict__ out) {
    int tok = blockIdx.x;
    int t   = threadIdx.x;
    int s1 = g_slot1[tok], s2 = g_slot2[tok];
    float g1 = (s1 >= 0) ? g_g1[tok] : 0.f;
    float g2 = (s2 >= 0) ? g_g2[tok] : 0.f;
    float4 v = make_float4(0.f, 0.f, 0.f, 0.f);
    if (s1 >= 0) {
        uint2 raw = ((const uint2*)(g_eouth + (size_t)s1 * DIMM))[t];
        float2 a0 = __half22float2(*(__half2*)&raw.x);
        float2 a1 = __half22float2(*(__half2*)&raw.y);
        v.x += g1 * a0.x; v.y += g1 * a0.y; v.z += g1 * a1.x; v.w += g1 * a1.y;
    }
    if (s2 >= 0) {
        uint2 raw = ((const uint2*)(g_eouth + (size_t)s2 * DIMM))[t];
        float2 a0 = __half22float2(*(__half2*)&raw.x);
        float2 a1 = __half22float2(*(__half2*)&raw.y);
        v.x += g2 * a0.x; v.y += g2 * a0.y; v.z += g2 * a1.x; v.w += g2 * a1.y;
    }
    ((float4*)(out + (size_t)tok * DIMM))[t] = v;
}

// -------------------------------- loss ---------------------------------------
__global__ void loss_part_kernel() {
    int be = blockIdx.x;
    int b = be / NE, e = be % NE;
    __shared__ float s[256];
    float acc = 0.f;
    for (int n = threadIdx.x; n < NN; n += 256)
        acc += g_probs[(size_t)(b * NN + n) * NE + e];
    s[threadIdx.x] = acc; __syncthreads();
    for (int off = 128; off; off >>= 1) {
        if (threadIdx.x < off) s[threadIdx.x] += s[threadIdx.x + off];
        __syncthreads();
    }
    if (threadIdx.x == 0)
        g_part_loss[be] = (s[0] / (float)NN) *
                          ((float)g_cnt_total[be] / (float)NN);
}

__global__ void loss_final_kernel(float* __restrict__ out) {
    __shared__ float s[64];
    int t = threadIdx.x;
    s[t] = g_part_loss[t]; __syncthreads();
    for (int off = 32; off; off >>= 1) {
        if (t < off) s[t] += s[t + off];
        __syncthreads();
    }
    if (t == 0) out[(size_t)NTOK * DIMM] = s[0] * 0.04f;
}

// ------------------------------- launch --------------------------------------
extern "C" void kernel_launch(void* const* d_in, const int* in_sizes, int n_in,
                              void* d_out, int out_size) {
    const float* x  = (const float*)d_in[0];
    const float* wg = (const float*)d_in[1];
    const float* w1 = (const float*)d_in[2];
    const float* w2 = (const float*)d_in[3];
    const float* b1 = (const float*)d_in[4];
    const float* b2 = (const float*)d_in[5];
    float* out = (float*)d_out;

    constexpr int SMEM = 3 * 35840;   // 107520
    cudaFuncSetAttribute(hgemm<DIMM, HID,  true >,
                         cudaFuncAttributeMaxDynamicSharedMemorySize, SMEM);
    cudaFuncSetAttribute(hgemm<HID,  DIMM, false>,
                         cudaFuncAttributeMaxDynamicSharedMemorySize, SMEM);

    const int W4 = NE * DIMM * HID / 4;
    gating_kernel<<<NTOK, 512>>>(x, wg);                                  // 0
    assign_kernel<<<BB * NE, 256>>>();                                    // 1
    gather_wconv1_kernel<<<NSLOT + 8192, 256>>>(x, (const float4*)w1, W4);// 2
    hgemm<DIMM, HID,  true ><<<(HID / 128) * (NSLOT / 128) + 2048, 256, SMEM>>>(
        b1, (const float4*)w2, W4);                                       // 3
    hgemm<HID,  DIMM, false><<<(DIMM / 128) * (NSLOT / 128), 256, SMEM>>>(
        b2, nullptr, 0);                                                  // 4
    combine_kernel<<<NTOK, 256>>>(out);                                   // 5
    loss_part_kernel<<<BB * NE, 256>>>();                                 // 6
    if (out_size > NTOK * DIMM)
        loss_final_kernel<<<1, 64>>>(out);                                // 7
}